// round 4
// baseline (speedup 1.0000x reference)
#include <cuda_runtime.h>
#include <cstdint>

// ---------------- problem constants ----------------
#define HH   48
#define WW   160
#define BB   32
#define CIn  32
#define CLn  32
#define NG   160            // 5*CL
#define CO_  64
#define HOo  24
#define WOo  80
#define CELLSZ 1024         // B*CL
#define DIRSZ  (HH*WW*CELLSZ)

// ---------------- device scratch (static: allocation-free) ----------------
__device__ float    g_xT[HH*WW*BB*CIn];      // [r][c][b][ci]
__device__ float    g_hd[4*DIRSZ];           // h per direction, scan coords
__device__ float    g_cd[4*DIRSZ];           // c per direction, scan coords
__device__ unsigned g_prog[4*HH];            // per-(dir,row) column progress
__device__ float    g_y [BB*CO_*HOo*WOo];    // pre-norm conv output
__device__ float    g_ps1[BB*HOo*CO_];       // per-block partial sums
__device__ float    g_ps2[BB*HOo*CO_];       // per-block partial sumsq
__device__ float    g_sc[CO_];
__device__ float    g_sh[CO_];

// ---------------- helpers ----------------
__device__ __forceinline__ unsigned ld_acq(const unsigned* p) {
    unsigned v;
    asm volatile("ld.acquire.gpu.global.u32 %0, [%1];" : "=r"(v) : "l"(p) : "memory");
    return v;
}
__device__ __forceinline__ void st_rel(unsigned* p, unsigned v) {
    asm volatile("st.release.gpu.global.u32 [%0], %1;" :: "l"(p), "r"(v) : "memory");
}
__device__ __forceinline__ float fsigmoid(float x) {
    float e = __expf(-x);
    return __fdividef(1.0f, 1.0f + e);
}
__device__ __forceinline__ float ftanh(float x) {
    float ax = fabsf(x);
    float e  = __expf(-2.0f * ax);          // in (0,1], never overflows
    float r  = __fdividef(1.0f - e, 1.0f + e);
    return copysignf(r, x);
}

// ---------------- kernel 0: transpose x + reset progress ----------------
__global__ void prep_kernel(const float* __restrict__ x) {
    int t = blockIdx.x * blockDim.x + threadIdx.x;   // 7680*256 threads, 1 float4 each
    if (t < 4*HH) g_prog[t] = 0;
    int i0 = t * 4;
    int ci = i0 & 31;
    int b  = (i0 >> 5) & 31;
    int c  = (i0 >> 10) % WW;
    int r  = i0 / (WW * CELLSZ);
    const float* xp = x + (((size_t)(b*CIn + ci))*HH + r)*WW + c;
    float4 v;
    v.x = xp[0];
    v.y = xp[(size_t)HH*WW];
    v.z = xp[2*(size_t)HH*WW];
    v.w = xp[3*(size_t)HH*WW];
    *(float4*)(g_xT + i0) = v;
}

// ---------------- kernel 1: 4-direction MDLSTM, row-pipelined ----------------
// smem floats: Ws[96*160] | As[32*100] | Zs[32*164] | Cl[1024] | Ct[1024] | Bs[160]
#define AP 100
#define ZP 164
#define SM_WS 0
#define SM_AS 15360
#define SM_ZS 18560
#define SM_CL 23808
#define SM_CT 24832
#define SM_BS 25856
#define SM_TOT 26016     // floats -> 104,064 bytes

__launch_bounds__(256, 2)
__global__ void mdlstm_kernel(const float* __restrict__ Wx, const float* __restrict__ Ul,
                              const float* __restrict__ Ut, const float* __restrict__ bias) {
    extern __shared__ float sm[];
    float* Ws = sm + SM_WS;    // [96][160]: k 0..31 x, 32..63 h_left, 64..95 h_top
    float* As = sm + SM_AS;    // [32][100]
    float* Zs = sm + SM_ZS;    // [32][164]
    float* Cl = sm + SM_CL;    // c_left [1024]
    float* Ct = sm + SM_CT;    // c_top  [1024]
    float* Bs = sm + SM_BS;    // bias   [160]

    const int tid = threadIdx.x;
    const int d   = blockIdx.x / HH;
    const int R   = blockIdx.x % HH;            // scan-row
    const bool flipH = (d >= 2);
    const bool flipW = (d & 1);
    const int r = flipH ? (HH-1-R) : R;         // original row

    // stage weights
    for (int i = tid; i < 32*NG; i += 256) {
        Ws[i]         = Wx[d*32*NG + i];
        Ws[32*NG + i] = Ul[d*32*NG + i];
        Ws[64*NG + i] = Ut[d*32*NG + i];
    }
    if (tid < NG) Bs[tid] = bias[d*NG + tid];
    // zero h_left / h_top regions of As, Cl, Ct
    for (int i = tid; i < 1024; i += 256) {
        int b = i >> 5, cl = i & 31;
        As[b*AP + 32 + cl] = 0.0f;
        As[b*AP + 64 + cl] = 0.0f;
        Cl[i] = 0.0f;
        Ct[i] = 0.0f;
    }
    __syncthreads();

    const int ab  = tid >> 3;            // GEMM: batch row
    const int g0  = (tid & 7) * 20;      // GEMM: 20 contiguous output cols
    const int gcl = tid & 31;            // gates: cell channel
    const int gb0 = (tid >> 5) * 4;      // gates: 4 batch rows
    unsigned* myprog  = &g_prog[d*HH + R];
    const unsigned* upprog = (R > 0) ? &g_prog[d*HH + R - 1] : 0;

    for (int Cs = 0; Cs < WW; ++Cs) {
        // ---- phase A: stage x and (h_top, c_top) ----
        {
            int c = flipW ? (WW-1-Cs) : Cs;
            float4 xv = *(const float4*)(g_xT + ((size_t)(r*WW + c))*CELLSZ + tid*4);
            *(float4*)(As + (tid>>3)*AP + ((tid&7)*4)) = xv;
        }
        if (R > 0) {
            if (tid == 0) { while ((int)ld_acq(upprog) <= Cs) { } }
            __syncthreads();
            size_t base = (((size_t)(d*HH + R - 1))*WW + Cs)*CELLSZ + tid*4;
            float4 hv = *(const float4*)(g_hd + base);
            float4 cv = *(const float4*)(g_cd + base);
            *(float4*)(As + (tid>>3)*AP + 64 + ((tid&7)*4)) = hv;
            *(float4*)(Ct + tid*4) = cv;
        }
        __syncthreads();

        // ---- GEMM: z[b][g] = bias[g] + sum_k A[b][k] * W[k][g] ----
        {
            unsigned long long acc[10];
            const unsigned long long* bp = (const unsigned long long*)(Bs + g0);
            #pragma unroll
            for (int j = 0; j < 10; ++j) acc[j] = bp[j];
            const float* arow = As + ab*AP;
            const float* wcol = Ws + g0;
            #pragma unroll 2
            for (int k = 0; k < 96; ++k) {
                float a = arow[k];
                unsigned long long aa;
                asm("mov.b64 %0, {%1, %1};" : "=l"(aa) : "f"(a));
                ulonglong2 wv[5];
                const ulonglong2* wp = (const ulonglong2*)(wcol + k*NG);
                #pragma unroll
                for (int j = 0; j < 5; ++j) wv[j] = wp[j];
                #pragma unroll
                for (int j = 0; j < 5; ++j) {
                    asm("fma.rn.f32x2 %0, %1, %2, %0;" : "+l"(acc[2*j])   : "l"(wv[j].x), "l"(aa));
                    asm("fma.rn.f32x2 %0, %1, %2, %0;" : "+l"(acc[2*j+1]) : "l"(wv[j].y), "l"(aa));
                }
            }
            ulonglong2* zp = (ulonglong2*)(Zs + ab*ZP + g0);
            #pragma unroll
            for (int j = 0; j < 5; ++j) {
                ulonglong2 t; t.x = acc[2*j]; t.y = acc[2*j+1];
                zp[j] = t;
            }
        }
        __syncthreads();

        // ---- gates ----
        {
            size_t cellbase = (((size_t)(d*HH + R))*WW + Cs)*CELLSZ;
            #pragma unroll
            for (int j = 0; j < 4; ++j) {
                int b = gb0 + j;
                const float* z = Zs + b*ZP + gcl;
                float zi  = z[0];
                float zfl = z[32];
                float zft = z[64];
                float zo  = z[96];
                float zg  = z[128];
                float cle = Cl[b*32 + gcl];
                float cto = Ct[b*32 + gcl];
                float cs = fsigmoid(zfl)*cle + fsigmoid(zft)*cto
                         + fsigmoid(zi)*ftanh(zg);
                float h  = fsigmoid(zo)*ftanh(cs);
                g_hd[cellbase + b*32 + gcl] = h;
                g_cd[cellbase + b*32 + gcl] = cs;
                As[b*AP + 32 + gcl] = h;     // h_left for next column
                Cl[b*32 + gcl]      = cs;    // c_left for next column
            }
        }
        __threadfence();
        __syncthreads();
        if (tid == 0) st_rel(myprog, (unsigned)(Cs + 1));
    }
}

// ---------------- kernel 2: 4-dir sum + 2x2/2 conv + tanh + partial stats ----------------
// smem: Hs[2*160*32 = 10240] | Wt[128*64 = 8192]  -> 73,728 bytes
__launch_bounds__(256, 2)
__global__ void conv_kernel(const float* __restrict__ conv_w, const float* __restrict__ conv_b) {
    extern __shared__ float sm2[];
    float* Hs = sm2;            // [rr][c][cl]
    float* Wt = sm2 + 10240;    // [cl*4+kh*2+kw][co]
    const int ho  = blockIdx.x;
    const int b   = blockIdx.y;
    const int tid = threadIdx.x;

    for (int i = tid; i < 128*64; i += 256) {
        int co = i & 63, q = i >> 6;
        Wt[i] = conv_w[co*128 + q];
    }
    for (int idx = tid; idx < 2*WW*32; idx += 256) {
        int cl = idx & 31;
        int c  = (idx >> 5) % WW;
        int rr = idx / (WW*32);
        int rg = 2*ho + rr;
        float v = 0.0f;
        #pragma unroll
        for (int d = 0; d < 4; ++d) {
            int Rd = (d >= 2) ? (HH-1-rg) : rg;
            int Cd = (d & 1)  ? (WW-1-c)  : c;
            v += g_hd[(((size_t)(d*HH + Rd))*WW + Cd)*CELLSZ + b*32 + cl];
        }
        Hs[idx] = v;
    }
    __syncthreads();

    const int co = tid >> 2;
    const int ws = tid & 3;
    float acc[20];
    #pragma unroll
    for (int j = 0; j < 20; ++j) acc[j] = 0.0f;

    for (int cl = 0; cl < 32; ++cl) {
        float w00 = Wt[(cl*4+0)*64 + co];
        float w01 = Wt[(cl*4+1)*64 + co];
        float w10 = Wt[(cl*4+2)*64 + co];
        float w11 = Wt[(cl*4+3)*64 + co];
        #pragma unroll
        for (int j = 0; j < 20; ++j) {
            int wo = j*4 + ws;
            int c0 = 2*wo;
            acc[j] += Hs[c0*32 + cl]            * w00
                    + Hs[(c0+1)*32 + cl]        * w01
                    + Hs[(WW + c0)*32 + cl]     * w10
                    + Hs[(WW + c0 + 1)*32 + cl] * w11;
        }
    }

    float bb = 4.0f * conv_b[co];
    float s1 = 0.0f, s2 = 0.0f;
    float* ybase = g_y + (((size_t)b*CO_ + co)*HOo + ho)*WOo;
    #pragma unroll
    for (int j = 0; j < 20; ++j) {
        int wo = j*4 + ws;
        float y = ftanh(acc[j] + bb);
        ybase[wo] = y;
        s1 += y;
        s2 += y*y;
    }
    // quad reduce across the 4 lanes holding the same co
    s1 += __shfl_down_sync(0xffffffffu, s1, 1, 4);
    s1 += __shfl_down_sync(0xffffffffu, s1, 2, 4);
    s2 += __shfl_down_sync(0xffffffffu, s2, 1, 4);
    s2 += __shfl_down_sync(0xffffffffu, s2, 2, 4);
    if (ws == 0) {
        int p = b*HOo + ho;
        g_ps1[p*CO_ + co] = s1;
        g_ps2[p*CO_ + co] = s2;
    }
}

// ---------------- kernel 3: per-channel mean/var -> scale/shift ----------------
__global__ void reduce_kernel(const float* __restrict__ gamma, const float* __restrict__ beta) {
    __shared__ float sh1[256];
    __shared__ float sh2[256];
    const int co = blockIdx.x;
    const int t  = threadIdx.x;
    float s1 = 0.0f, s2 = 0.0f;
    for (int p = t; p < BB*HOo; p += 256) {
        s1 += g_ps1[p*CO_ + co];
        s2 += g_ps2[p*CO_ + co];
    }
    sh1[t] = s1; sh2[t] = s2;
    __syncthreads();
    for (int s = 128; s > 0; s >>= 1) {
        if (t < s) { sh1[t] += sh1[t+s]; sh2[t] += sh2[t+s]; }
        __syncthreads();
    }
    if (t == 0) {
        const float N = (float)(BB*HOo*WOo);
        float mean = sh1[0] / N;
        float var  = sh2[0] / N - mean*mean;
        float sc = gamma[co] * rsqrtf(var + 1e-5f);
        g_sc[co] = sc;
        g_sh[co] = beta[co] - mean*sc;
    }
}

// ---------------- kernel 4: normalize ----------------
__global__ void norm_kernel(float* __restrict__ out) {
    int t  = blockIdx.x * blockDim.x + threadIdx.x;  // 983040 threads
    int i0 = t * 4;
    int co = (i0 / (HOo*WOo)) & 63;
    float sc = g_sc[co], sh = g_sh[co];
    float4 v = *(const float4*)(g_y + i0);
    v.x = v.x*sc + sh;
    v.y = v.y*sc + sh;
    v.z = v.z*sc + sh;
    v.w = v.w*sc + sh;
    *(float4*)(out + i0) = v;
}

// ---------------- launcher ----------------
extern "C" void kernel_launch(void* const* d_in, const int* in_sizes, int n_in,
                              void* d_out, int out_size) {
    (void)in_sizes; (void)n_in; (void)out_size;
    const float* x      = (const float*)d_in[0];
    const float* Wx     = (const float*)d_in[1];
    const float* Ul     = (const float*)d_in[2];
    const float* Ut     = (const float*)d_in[3];
    const float* bias   = (const float*)d_in[4];
    const float* conv_w = (const float*)d_in[5];
    const float* conv_b = (const float*)d_in[6];
    const float* gamma  = (const float*)d_in[7];
    const float* beta   = (const float*)d_in[8];
    float* out = (float*)d_out;

    cudaFuncSetAttribute(mdlstm_kernel, cudaFuncAttributeMaxDynamicSharedMemorySize, SM_TOT*4);
    cudaFuncSetAttribute(conv_kernel,   cudaFuncAttributeMaxDynamicSharedMemorySize, (10240+8192)*4);

    prep_kernel<<<7680, 256>>>(x);
    mdlstm_kernel<<<4*HH, 256, SM_TOT*4>>>(Wx, Ul, Ut, bias);
    conv_kernel<<<dim3(HOo, BB), 256, (10240+8192)*4>>>(conv_w, conv_b);
    reduce_kernel<<<CO_, 256>>>(gamma, beta);
    norm_kernel<<<3840, 256>>>(out);
}

// round 5
// speedup vs baseline: 1.3955x; 1.3955x over previous
#include <cuda_runtime.h>
#include <cstdint>

// ---------------- problem constants ----------------
#define HH   48
#define WW   160
#define BB   32
#define CIn  32
#define NG   160            // 5*CL
#define CO_  64
#define HOo  24
#define WOo  80
#define CELLSZ 1024         // B*CL
#define DIRSZ  (HH*WW*CELLSZ)
#define NPAIR 24            // HH/2

// ---------------- device scratch (static: allocation-free) ----------------
__device__ float    g_xT[HH*WW*BB*CIn];      // [r][c][b][ci]
__device__ float    g_hd[4*DIRSZ];           // h per direction, scan coords
__device__ float    g_cd[4*DIRSZ];           // c per direction, scan coords (odd rows only used)
__device__ unsigned g_prog[4*NPAIR];         // per-(dir,pair) boundary-row progress
__device__ float    g_y [BB*CO_*HOo*WOo];    // pre-norm conv output
__device__ float    g_ps1[BB*HOo*CO_];
__device__ float    g_ps2[BB*HOo*CO_];
__device__ float    g_sc[CO_];
__device__ float    g_sh[CO_];

// ---------------- helpers ----------------
__device__ __forceinline__ unsigned ld_acq(const unsigned* p) {
    unsigned v;
    asm volatile("ld.acquire.gpu.global.u32 %0, [%1];" : "=r"(v) : "l"(p) : "memory");
    return v;
}
__device__ __forceinline__ void st_rel(unsigned* p, unsigned v) {
    asm volatile("st.release.gpu.global.u32 [%0], %1;" :: "l"(p), "r"(v) : "memory");
}
__device__ __forceinline__ float fsigmoid(float x) {
    float e = __expf(-x);
    return __fdividef(1.0f, 1.0f + e);
}
__device__ __forceinline__ float ftanh(float x) {
    float ax = fabsf(x);
    float e  = __expf(-2.0f * ax);          // in (0,1], never overflows
    float r  = __fdividef(1.0f - e, 1.0f + e);
    return copysignf(r, x);
}

// ---------------- kernel 0: transpose x + reset progress ----------------
__global__ void prep_kernel(const float* __restrict__ x) {
    int t = blockIdx.x * blockDim.x + threadIdx.x;   // 7680*256 threads, 1 float4 each
    if (t < 4*NPAIR) g_prog[t] = 0;
    int i0 = t * 4;
    int ci = i0 & 31;
    int b  = (i0 >> 5) & 31;
    int c  = (i0 >> 10) % WW;
    int r  = i0 / (WW * CELLSZ);
    const float* xp = x + (((size_t)(b*CIn + ci))*HH + r)*WW + c;
    float4 v;
    v.x = xp[0];
    v.y = xp[(size_t)HH*WW];
    v.z = xp[2*(size_t)HH*WW];
    v.w = xp[3*(size_t)HH*WW];
    *(float4*)(g_xT + i0) = v;
}

// ---------------- kernel 1: 4-direction MDLSTM, paired rows, 96 CTAs ----------------
// smem floats:
//   Ws [96*160]=15360 | Bs[160] | As[64*100]=6400 | Zs[64*164]=10496
//   Cl[2048] | Ct0[1024] | Ct1[1024]
#define AP 100
#define ZP 164
#define SM_WS  0
#define SM_BS  15360
#define SM_AS  15520
#define SM_ZS  21920
#define SM_CL  32416
#define SM_CT0 34464
#define SM_CT1 35488
#define SM_TOT 36512     // floats -> 146,048 bytes

__launch_bounds__(256, 1)
__global__ void mdlstm_kernel(const float* __restrict__ Wx, const float* __restrict__ Ul,
                              const float* __restrict__ Ut, const float* __restrict__ bias) {
    extern __shared__ float sm[];
    float* Ws  = sm + SM_WS;    // [96][160]: k 0..31 Wx, 32..63 Ul, 64..95 Ut
    float* Bs  = sm + SM_BS;
    float* As  = sm + SM_AS;    // [64][100]: rows 0..31 cell0, 32..63 cell1; cols: x|h_left|h_top
    float* Zs  = sm + SM_ZS;    // [64][164]
    float* Cl  = sm + SM_CL;    // c_left  [64*32]
    float* Ct0 = sm + SM_CT0;   // c_top for cell0 (external) [1024]
    float* Ct1 = sm + SM_CT1;   // c_top for cell1 (= c(r0, prev col)) [1024]

    const int tid = threadIdx.x;
    const int d   = blockIdx.x / NPAIR;
    const int p   = blockIdx.x % NPAIR;
    const bool flipH = (d >= 2);
    const bool flipW = (d & 1);
    const int r0  = 2*p;                         // scan rows
    const int r1  = 2*p + 1;
    const int r0o = flipH ? (HH-1-r0) : r0;      // original rows
    const int r1o = flipH ? (HH-1-r1) : r1;

    // stage weights + bias
    for (int i = tid; i < 32*NG; i += 256) {
        Ws[i]         = Wx[d*32*NG + i];
        Ws[32*NG + i] = Ul[d*32*NG + i];
        Ws[64*NG + i] = Ut[d*32*NG + i];
    }
    if (tid < NG) Bs[tid] = bias[d*NG + tid];
    // zero h_left/h_top slots and c states
    for (int i = tid; i < 2048; i += 256) {
        int row = i >> 5, cl = i & 31;
        As[row*AP + 32 + cl] = 0.0f;   // h_left
        As[row*AP + 64 + cl] = 0.0f;   // h_top
        Cl[i] = 0.0f;
        if (i < 1024) { Ct0[i] = 0.0f; Ct1[i] = 0.0f; }
    }
    __syncthreads();

    const int rg  = tid >> 3;            // GEMM: A-row pair index (rows 2rg, 2rg+1)
    const int cg  = tid & 7;             // GEMM: 20 contiguous output cols
    const int gcl = tid & 31;            // gates: cell channel
    const int gb0 = (tid >> 5) * 8;      // gates: 8 A-rows each
    unsigned* myflag = &g_prog[d*NPAIR + p];
    const unsigned* upflag = (p > 0) ? &g_prog[d*NPAIR + p - 1] : 0;

    for (int t = 0; t <= WW; ++t) {
        // ---- staging ----
        if (t < WW) {
            if (p > 0) {
                if (tid == 0) { while ((int)ld_acq(upflag) < t + 1) { } }
                __syncthreads();
            }
            int c = flipW ? (WW-1-t) : t;
            float4 xv = *(const float4*)(g_xT + ((size_t)(r0o*WW + c))*CELLSZ + tid*4);
            *(float4*)(As + (tid>>3)*AP + ((tid&7)*4)) = xv;
            if (p > 0) {
                size_t hb = (((size_t)(d*HH + r0 - 1))*WW + t)*CELLSZ + tid*4;
                float4 hv = *(const float4*)(g_hd + hb);
                float4 cv = *(const float4*)(g_cd + hb);
                *(float4*)(As + (tid>>3)*AP + 64 + ((tid&7)*4)) = hv;
                *(float4*)(Ct0 + tid*4) = cv;
            }
        }
        if (t >= 1) {
            int c1 = t - 1;
            int c  = flipW ? (WW-1-c1) : c1;
            float4 xv = *(const float4*)(g_xT + ((size_t)(r1o*WW + c))*CELLSZ + tid*4);
            *(float4*)(As + (32 + (tid>>3))*AP + ((tid&7)*4)) = xv;
        }
        __syncthreads();

        // ---- batched GEMM: Z[64][160] = A[64][96] @ W[96][160] + bias ----
        {
            unsigned long long acc0[10], acc1[10];
            const ulonglong2* bp = (const ulonglong2*)(Bs + cg*20);
            #pragma unroll
            for (int j = 0; j < 5; ++j) {
                ulonglong2 bv = bp[j];
                acc0[2*j] = bv.x; acc0[2*j+1] = bv.y;
                acc1[2*j] = bv.x; acc1[2*j+1] = bv.y;
            }
            const float* arow0 = As + (2*rg)*AP;
            const float* arow1 = arow0 + AP;
            const float* wcol  = Ws + cg*20;
            #pragma unroll 2
            for (int k = 0; k < 96; ++k) {
                float a0 = arow0[k];
                float a1 = arow1[k];
                unsigned long long aa0, aa1;
                asm("mov.b64 %0, {%1, %1};" : "=l"(aa0) : "f"(a0));
                asm("mov.b64 %0, {%1, %1};" : "=l"(aa1) : "f"(a1));
                const ulonglong2* wp = (const ulonglong2*)(wcol + k*NG);
                #pragma unroll
                for (int j = 0; j < 5; ++j) {
                    ulonglong2 wv = wp[j];
                    asm("fma.rn.f32x2 %0, %1, %2, %0;" : "+l"(acc0[2*j])   : "l"(wv.x), "l"(aa0));
                    asm("fma.rn.f32x2 %0, %1, %2, %0;" : "+l"(acc0[2*j+1]) : "l"(wv.y), "l"(aa0));
                    asm("fma.rn.f32x2 %0, %1, %2, %0;" : "+l"(acc1[2*j])   : "l"(wv.x), "l"(aa1));
                    asm("fma.rn.f32x2 %0, %1, %2, %0;" : "+l"(acc1[2*j+1]) : "l"(wv.y), "l"(aa1));
                }
            }
            ulonglong2* zp0 = (ulonglong2*)(Zs + (2*rg)*ZP + cg*20);
            ulonglong2* zp1 = (ulonglong2*)(Zs + (2*rg+1)*ZP + cg*20);
            #pragma unroll
            for (int j = 0; j < 5; ++j) {
                ulonglong2 v0; v0.x = acc0[2*j]; v0.y = acc0[2*j+1]; zp0[j] = v0;
                ulonglong2 v1; v1.x = acc1[2*j]; v1.y = acc1[2*j+1]; zp1[j] = v1;
            }
        }
        __syncthreads();

        // ---- gates for both cells ----
        {
            const bool act0 = (t < WW);
            const bool act1 = (t >= 1);
            size_t base0 = (((size_t)(d*HH + r0))*WW + t)*CELLSZ;
            size_t base1 = (((size_t)(d*HH + r1))*WW + (t-1))*CELLSZ;
            #pragma unroll
            for (int j = 0; j < 8; ++j) {
                int gr = gb0 + j;
                const float* z = Zs + gr*ZP + gcl;
                float zi  = z[0];
                float zfl = z[32];
                float zft = z[64];
                float zo  = z[96];
                float zg  = z[128];
                int b = gr & 31;
                float cle = Cl[gr*32 + gcl];
                float cto = (gr < 32) ? Ct0[b*32 + gcl] : Ct1[b*32 + gcl];
                float cs = fsigmoid(zfl)*cle + fsigmoid(zft)*cto
                         + fsigmoid(zi)*ftanh(zg);
                float h  = fsigmoid(zo)*ftanh(cs);
                if (gr < 32) {
                    if (act0) {
                        Cl[gr*32 + gcl]        = cs;
                        As[gr*AP + 32 + gcl]   = h;       // h_left(r0)
                        Ct1[b*32 + gcl]        = cs;      // c_top for cell1 next step
                        As[(32+b)*AP + 64 + gcl] = h;     // h_top for cell1 next step
                        g_hd[base0 + b*32 + gcl] = h;
                    }
                } else {
                    if (act1) {
                        Cl[gr*32 + gcl]        = cs;
                        As[gr*AP + 32 + gcl]   = h;       // h_left(r1)
                        g_hd[base1 + b*32 + gcl] = h;     // boundary row -> next CTA + conv
                        g_cd[base1 + b*32 + gcl] = cs;
                    }
                }
            }
        }
        __threadfence();
        __syncthreads();
        if (tid == 0 && t >= 1) st_rel(myflag, (unsigned)t);
    }
}

// ---------------- kernel 2: 4-dir sum + 2x2/2 conv + tanh + partial stats ----------------
__launch_bounds__(256, 2)
__global__ void conv_kernel(const float* __restrict__ conv_w, const float* __restrict__ conv_b) {
    extern __shared__ float sm2[];
    float* Hs = sm2;            // [rr][c][cl]  2*160*32
    float* Wt = sm2 + 10240;    // [cl*4+kh*2+kw][co] 128*64
    const int ho  = blockIdx.x;
    const int b   = blockIdx.y;
    const int tid = threadIdx.x;

    for (int i = tid; i < 128*64; i += 256) {
        int co = i & 63, q = i >> 6;
        Wt[i] = conv_w[co*128 + q];
    }
    for (int idx = tid; idx < 2*WW*32; idx += 256) {
        int cl = idx & 31;
        int c  = (idx >> 5) % WW;
        int rr = idx / (WW*32);
        int rg = 2*ho + rr;
        float v = 0.0f;
        #pragma unroll
        for (int d = 0; d < 4; ++d) {
            int Rd = (d >= 2) ? (HH-1-rg) : rg;
            int Cd = (d & 1)  ? (WW-1-c)  : c;
            v += g_hd[(((size_t)(d*HH + Rd))*WW + Cd)*CELLSZ + b*32 + cl];
        }
        Hs[idx] = v;
    }
    __syncthreads();

    const int co = tid >> 2;
    const int ws = tid & 3;
    float acc[20];
    #pragma unroll
    for (int j = 0; j < 20; ++j) acc[j] = 0.0f;

    for (int cl = 0; cl < 32; ++cl) {
        float w00 = Wt[(cl*4+0)*64 + co];
        float w01 = Wt[(cl*4+1)*64 + co];
        float w10 = Wt[(cl*4+2)*64 + co];
        float w11 = Wt[(cl*4+3)*64 + co];
        #pragma unroll
        for (int j = 0; j < 20; ++j) {
            int wo = j*4 + ws;
            int c0 = 2*wo;
            acc[j] += Hs[c0*32 + cl]            * w00
                    + Hs[(c0+1)*32 + cl]        * w01
                    + Hs[(WW + c0)*32 + cl]     * w10
                    + Hs[(WW + c0 + 1)*32 + cl] * w11;
        }
    }

    float bb = 4.0f * conv_b[co];
    float s1 = 0.0f, s2 = 0.0f;
    float* ybase = g_y + (((size_t)b*CO_ + co)*HOo + ho)*WOo;
    #pragma unroll
    for (int j = 0; j < 20; ++j) {
        int wo = j*4 + ws;
        float y = ftanh(acc[j] + bb);
        ybase[wo] = y;
        s1 += y;
        s2 += y*y;
    }
    s1 += __shfl_down_sync(0xffffffffu, s1, 1, 4);
    s1 += __shfl_down_sync(0xffffffffu, s1, 2, 4);
    s2 += __shfl_down_sync(0xffffffffu, s2, 1, 4);
    s2 += __shfl_down_sync(0xffffffffu, s2, 2, 4);
    if (ws == 0) {
        int pp = b*HOo + ho;
        g_ps1[pp*CO_ + co] = s1;
        g_ps2[pp*CO_ + co] = s2;
    }
}

// ---------------- kernel 3: per-channel mean/var -> scale/shift ----------------
__global__ void reduce_kernel(const float* __restrict__ gamma, const float* __restrict__ beta) {
    __shared__ float sh1[256];
    __shared__ float sh2[256];
    const int co = blockIdx.x;
    const int t  = threadIdx.x;
    float s1 = 0.0f, s2 = 0.0f;
    for (int p = t; p < BB*HOo; p += 256) {
        s1 += g_ps1[p*CO_ + co];
        s2 += g_ps2[p*CO_ + co];
    }
    sh1[t] = s1; sh2[t] = s2;
    __syncthreads();
    for (int s = 128; s > 0; s >>= 1) {
        if (t < s) { sh1[t] += sh1[t+s]; sh2[t] += sh2[t+s]; }
        __syncthreads();
    }
    if (t == 0) {
        const float N = (float)(BB*HOo*WOo);
        float mean = sh1[0] / N;
        float var  = sh2[0] / N - mean*mean;
        float sc = gamma[co] * rsqrtf(var + 1e-5f);
        g_sc[co] = sc;
        g_sh[co] = beta[co] - mean*sc;
    }
}

// ---------------- kernel 4: normalize ----------------
__global__ void norm_kernel(float* __restrict__ out) {
    int t  = blockIdx.x * blockDim.x + threadIdx.x;
    int i0 = t * 4;
    int co = (i0 / (HOo*WOo)) & 63;
    float sc = g_sc[co], sh = g_sh[co];
    float4 v = *(const float4*)(g_y + i0);
    v.x = v.x*sc + sh;
    v.y = v.y*sc + sh;
    v.z = v.z*sc + sh;
    v.w = v.w*sc + sh;
    *(float4*)(out + i0) = v;
}

// ---------------- launcher ----------------
extern "C" void kernel_launch(void* const* d_in, const int* in_sizes, int n_in,
                              void* d_out, int out_size) {
    (void)in_sizes; (void)n_in; (void)out_size;
    const float* x      = (const float*)d_in[0];
    const float* Wx     = (const float*)d_in[1];
    const float* Ul     = (const float*)d_in[2];
    const float* Ut     = (const float*)d_in[3];
    const float* bias   = (const float*)d_in[4];
    const float* conv_w = (const float*)d_in[5];
    const float* conv_b = (const float*)d_in[6];
    const float* gamma  = (const float*)d_in[7];
    const float* beta   = (const float*)d_in[8];
    float* out = (float*)d_out;

    cudaFuncSetAttribute(mdlstm_kernel, cudaFuncAttributeMaxDynamicSharedMemorySize, SM_TOT*4);
    cudaFuncSetAttribute(conv_kernel,   cudaFuncAttributeMaxDynamicSharedMemorySize, (10240+8192)*4);

    prep_kernel<<<7680, 256>>>(x);
    mdlstm_kernel<<<4*NPAIR, 256, SM_TOT*4>>>(Wx, Ul, Ut, bias);
    conv_kernel<<<dim3(HOo, BB), 256, (10240+8192)*4>>>(conv_w, conv_b);
    reduce_kernel<<<CO_, 256>>>(gamma, beta);
    norm_kernel<<<3840, 256>>>(out);
}

// round 6
// speedup vs baseline: 1.4796x; 1.0603x over previous
#include <cuda_runtime.h>
#include <cstdint>

// ---------------- problem constants ----------------
#define HH   48
#define WW   160
#define BB   32
#define CIn  32
#define NG   160            // 5*CL
#define CO_  64
#define HOo  24
#define WOo  80
#define CELLSZ 1024         // B*CL
#define DIRSZ  (HH*WW*CELLSZ)
#define NPAIR 24            // HH/2

// ---------------- device scratch (static: allocation-free) ----------------
__device__ float    g_xT[HH*WW*BB*CIn];      // [r][c][b][ci]
__device__ float    g_hd[4*DIRSZ];           // h per direction, scan coords
__device__ float    g_cd[4*DIRSZ];           // c per direction (odd rows used)
__device__ unsigned g_prog[4*NPAIR];         // per-(dir,pair) boundary progress
__device__ float    g_y [BB*CO_*HOo*WOo];    // pre-norm conv output
__device__ float    g_ps1[BB*HOo*CO_];
__device__ float    g_ps2[BB*HOo*CO_];
__device__ float    g_sc[CO_];
__device__ float    g_sh[CO_];

// ---------------- helpers ----------------
__device__ __forceinline__ unsigned ld_acq(const unsigned* p) {
    unsigned v;
    asm volatile("ld.acquire.gpu.global.u32 %0, [%1];" : "=r"(v) : "l"(p) : "memory");
    return v;
}
__device__ __forceinline__ void st_rel(unsigned* p, unsigned v) {
    asm volatile("st.release.gpu.global.u32 [%0], %1;" :: "l"(p), "r"(v) : "memory");
}
__device__ __forceinline__ float fsigmoid(float x) {
    float e = __expf(-x);
    return __fdividef(1.0f, 1.0f + e);
}
__device__ __forceinline__ float ftanh(float x) {
    float ax = fabsf(x);
    float e  = __expf(-2.0f * ax);          // in (0,1], never overflows
    float r  = __fdividef(1.0f - e, 1.0f + e);
    return copysignf(r, x);
}

// ---------------- kernel 0: transpose x + reset progress ----------------
__global__ void prep_kernel(const float* __restrict__ x) {
    int t = blockIdx.x * blockDim.x + threadIdx.x;   // 7680*256 threads, 1 float4 each
    if (t < 4*NPAIR) g_prog[t] = 0;
    int i0 = t * 4;
    int ci = i0 & 31;
    int b  = (i0 >> 5) & 31;
    int c  = (i0 >> 10) % WW;
    int r  = i0 / (WW * CELLSZ);
    const float* xp = x + (((size_t)(b*CIn + ci))*HH + r)*WW + c;
    float4 v;
    v.x = xp[0];
    v.y = xp[(size_t)HH*WW];
    v.z = xp[2*(size_t)HH*WW];
    v.w = xp[3*(size_t)HH*WW];
    *(float4*)(g_xT + i0) = v;
}

// ---------------- kernel 1: 4-direction MDLSTM, paired rows, 96 CTAs ----------------
#define AP 100
#define ZP 164
#define SM_WS  0
#define SM_BS  15360
#define SM_AS  15520
#define SM_ZS  21920
#define SM_CL  32416
#define SM_CT0 34464
#define SM_CT1 35488
#define SM_TOT 36512     // floats -> 146,048 bytes

__launch_bounds__(256, 1)
__global__ void mdlstm_kernel(const float* __restrict__ Wx, const float* __restrict__ Ul,
                              const float* __restrict__ Ut, const float* __restrict__ bias) {
    extern __shared__ float sm[];
    float* Ws  = sm + SM_WS;    // [96][160]: k 0..31 Wx, 32..63 Ul, 64..95 Ut
    float* Bs  = sm + SM_BS;
    float* As  = sm + SM_AS;    // [64][100]: rows 0..31 cell0, 32..63 cell1
    float* Zs  = sm + SM_ZS;    // [64][164]
    float* Cl  = sm + SM_CL;    // c_left [64*32]
    float* Ct0 = sm + SM_CT0;   // c_top for cell0 (external)
    float* Ct1 = sm + SM_CT1;   // c_top for cell1 (= c(r0, prev col))

    const int tid = threadIdx.x;
    const int d   = blockIdx.x / NPAIR;
    const int p   = blockIdx.x % NPAIR;
    const bool flipH = (d >= 2);
    const bool flipW = (d & 1);
    const int r0  = 2*p;
    const int r1  = 2*p + 1;
    const int r0o = flipH ? (HH-1-r0) : r0;
    const int r1o = flipH ? (HH-1-r1) : r1;

    for (int i = tid; i < 32*NG; i += 256) {
        Ws[i]         = Wx[d*32*NG + i];
        Ws[32*NG + i] = Ul[d*32*NG + i];
        Ws[64*NG + i] = Ut[d*32*NG + i];
    }
    if (tid < NG) Bs[tid] = bias[d*NG + tid];
    for (int i = tid; i < 2048; i += 256) {
        int row = i >> 5, cl = i & 31;
        As[row*AP + 32 + cl] = 0.0f;
        As[row*AP + 64 + cl] = 0.0f;
        Cl[i] = 0.0f;
        if (i < 1024) { Ct0[i] = 0.0f; Ct1[i] = 0.0f; }
    }
    __syncthreads();

    const int rg  = tid >> 3;            // GEMM: row-pair index
    const int cg  = tid & 7;             // GEMM: 20 contiguous output cols
    const int gcl = tid & 31;            // gates: cell channel
    const int gb0 = (tid >> 5) * 8;      // gates: 8 A-rows each
    unsigned* myflag = &g_prog[d*NPAIR + p];
    const unsigned* upflag = (p > 0) ? &g_prog[d*NPAIR + p - 1] : 0;

    // bias slice held in registers (f32x2 pairs)
    unsigned long long breg[10];
    {
        const ulonglong2* bp = (const ulonglong2*)(Bs + cg*20);
        #pragma unroll
        for (int j = 0; j < 5; ++j) {
            ulonglong2 bv = bp[j];
            breg[2*j] = bv.x; breg[2*j+1] = bv.y;
        }
    }

    for (int t = 0; t <= WW; ++t) {
        // ---- staging: issue x LDGs first so their latency hides under the spin ----
        float4 xv0, xv1;
        if (t < WW) {
            int c = flipW ? (WW-1-t) : t;
            xv0 = *(const float4*)(g_xT + ((size_t)(r0o*WW + c))*CELLSZ + tid*4);
        }
        if (t >= 1) {
            int c1 = t - 1;
            int c  = flipW ? (WW-1-c1) : c1;
            xv1 = *(const float4*)(g_xT + ((size_t)(r1o*WW + c))*CELLSZ + tid*4);
        }
        if (t < WW && p > 0) {
            if (tid == 0) { while ((int)ld_acq(upflag) < t + 1) { } }
            __syncthreads();
            size_t hb = (((size_t)(d*HH + r0 - 1))*WW + t)*CELLSZ + tid*4;
            float4 hv = *(const float4*)(g_hd + hb);
            float4 cv = *(const float4*)(g_cd + hb);
            *(float4*)(As + (tid>>3)*AP + 64 + ((tid&7)*4)) = hv;
            *(float4*)(Ct0 + tid*4) = cv;
        }
        if (t < WW) *(float4*)(As + (tid>>3)*AP + ((tid&7)*4)) = xv0;
        if (t >= 1) *(float4*)(As + (32 + (tid>>3))*AP + ((tid&7)*4)) = xv1;
        __syncthreads();

        // ---- batched GEMM: Z[64][160] = A[64][96] @ W[96][160] + bias ----
        {
            unsigned long long acc0[10], acc1[10];
            #pragma unroll
            for (int j = 0; j < 10; ++j) { acc0[j] = breg[j]; acc1[j] = breg[j]; }
            const float* arow0 = As + (2*rg)*AP;
            const float* arow1 = arow0 + AP;
            const float* wcol  = Ws + cg*20;
            #pragma unroll 2
            for (int k0 = 0; k0 < 96; k0 += 8) {
                float4 a0lo = *(const float4*)(arow0 + k0);
                float4 a0hi = *(const float4*)(arow0 + k0 + 4);
                float4 a1lo = *(const float4*)(arow1 + k0);
                float4 a1hi = *(const float4*)(arow1 + k0 + 4);
                float a0s[8] = {a0lo.x, a0lo.y, a0lo.z, a0lo.w, a0hi.x, a0hi.y, a0hi.z, a0hi.w};
                float a1s[8] = {a1lo.x, a1lo.y, a1lo.z, a1lo.w, a1hi.x, a1hi.y, a1hi.z, a1hi.w};
                #pragma unroll
                for (int kk = 0; kk < 8; ++kk) {
                    unsigned long long aa0, aa1;
                    asm("mov.b64 %0, {%1, %1};" : "=l"(aa0) : "f"(a0s[kk]));
                    asm("mov.b64 %0, {%1, %1};" : "=l"(aa1) : "f"(a1s[kk]));
                    const ulonglong2* wp = (const ulonglong2*)(wcol + (k0 + kk)*NG);
                    #pragma unroll
                    for (int j = 0; j < 5; ++j) {
                        ulonglong2 wv = wp[j];
                        asm("fma.rn.f32x2 %0, %1, %2, %0;" : "+l"(acc0[2*j])   : "l"(wv.x), "l"(aa0));
                        asm("fma.rn.f32x2 %0, %1, %2, %0;" : "+l"(acc0[2*j+1]) : "l"(wv.y), "l"(aa0));
                        asm("fma.rn.f32x2 %0, %1, %2, %0;" : "+l"(acc1[2*j])   : "l"(wv.x), "l"(aa1));
                        asm("fma.rn.f32x2 %0, %1, %2, %0;" : "+l"(acc1[2*j+1]) : "l"(wv.y), "l"(aa1));
                    }
                }
            }
            ulonglong2* zp0 = (ulonglong2*)(Zs + (2*rg)*ZP + cg*20);
            ulonglong2* zp1 = (ulonglong2*)(Zs + (2*rg+1)*ZP + cg*20);
            #pragma unroll
            for (int j = 0; j < 5; ++j) {
                ulonglong2 v0; v0.x = acc0[2*j]; v0.y = acc0[2*j+1]; zp0[j] = v0;
                ulonglong2 v1; v1.x = acc1[2*j]; v1.y = acc1[2*j+1]; zp1[j] = v1;
            }
        }
        __syncthreads();

        // ---- gates for both cells ----
        {
            const bool act0 = (t < WW);
            const bool act1 = (t >= 1);
            size_t base0 = (((size_t)(d*HH + r0))*WW + t)*CELLSZ;
            size_t base1 = (((size_t)(d*HH + r1))*WW + (t-1))*CELLSZ;
            #pragma unroll
            for (int j = 0; j < 8; ++j) {
                int gr = gb0 + j;
                const float* z = Zs + gr*ZP + gcl;
                float zi  = z[0];
                float zfl = z[32];
                float zft = z[64];
                float zo  = z[96];
                float zg  = z[128];
                int b = gr & 31;
                float cle = Cl[gr*32 + gcl];
                float cto = (gr < 32) ? Ct0[b*32 + gcl] : Ct1[b*32 + gcl];
                float cs = fsigmoid(zfl)*cle + fsigmoid(zft)*cto
                         + fsigmoid(zi)*ftanh(zg);
                float h  = fsigmoid(zo)*ftanh(cs);
                if (gr < 32) {
                    if (act0) {
                        Cl[gr*32 + gcl]          = cs;
                        As[gr*AP + 32 + gcl]     = h;     // h_left(r0)
                        Ct1[b*32 + gcl]          = cs;    // c_top for cell1 next step
                        As[(32+b)*AP + 64 + gcl] = h;     // h_top for cell1 next step
                        g_hd[base0 + b*32 + gcl] = h;
                    }
                } else {
                    if (act1) {
                        Cl[gr*32 + gcl]          = cs;
                        As[gr*AP + 32 + gcl]     = h;     // h_left(r1)
                        g_hd[base1 + b*32 + gcl] = h;     // boundary row
                        g_cd[base1 + b*32 + gcl] = cs;
                    }
                }
            }
        }
        __syncthreads();
        // bar.sync orders all threads' boundary STGs before tid0; tid0's gpu
        // fence + release-store publishes them to the downstream CTA.
        if (tid == 0 && t >= 1) {
            __threadfence();
            st_rel(myflag, (unsigned)t);
        }
    }
}

// ---------------- kernel 2: 4-dir sum + 2x2/2 conv + tanh + partial stats ----------------
__launch_bounds__(256, 2)
__global__ void conv_kernel(const float* __restrict__ conv_w, const float* __restrict__ conv_b) {
    extern __shared__ float sm2[];
    float* Hs = sm2;            // [rr][c][cl]  2*160*32
    float* Wt = sm2 + 10240;    // [cl*4+kh*2+kw][co] 128*64
    const int ho  = blockIdx.x;
    const int b   = blockIdx.y;
    const int tid = threadIdx.x;

    for (int i = tid; i < 128*64; i += 256) {
        int co = i & 63, q = i >> 6;
        Wt[i] = conv_w[co*128 + q];
    }
    for (int idx = tid; idx < 2*WW*32; idx += 256) {
        int cl = idx & 31;
        int c  = (idx >> 5) % WW;
        int rr = idx / (WW*32);
        int rg = 2*ho + rr;
        float v = 0.0f;
        #pragma unroll
        for (int d = 0; d < 4; ++d) {
            int Rd = (d >= 2) ? (HH-1-rg) : rg;
            int Cd = (d & 1)  ? (WW-1-c)  : c;
            v += g_hd[(((size_t)(d*HH + Rd))*WW + Cd)*CELLSZ + b*32 + cl];
        }
        Hs[idx] = v;
    }
    __syncthreads();

    const int co = tid >> 2;
    const int ws = tid & 3;
    float acc[20];
    #pragma unroll
    for (int j = 0; j < 20; ++j) acc[j] = 0.0f;

    for (int cl = 0; cl < 32; ++cl) {
        float w00 = Wt[(cl*4+0)*64 + co];
        float w01 = Wt[(cl*4+1)*64 + co];
        float w10 = Wt[(cl*4+2)*64 + co];
        float w11 = Wt[(cl*4+3)*64 + co];
        #pragma unroll
        for (int j = 0; j < 20; ++j) {
            int wo = j*4 + ws;
            int c0 = 2*wo;
            acc[j] += Hs[c0*32 + cl]            * w00
                    + Hs[(c0+1)*32 + cl]        * w01
                    + Hs[(WW + c0)*32 + cl]     * w10
                    + Hs[(WW + c0 + 1)*32 + cl] * w11;
        }
    }

    float bb = 4.0f * conv_b[co];
    float s1 = 0.0f, s2 = 0.0f;
    float* ybase = g_y + (((size_t)b*CO_ + co)*HOo + ho)*WOo;
    #pragma unroll
    for (int j = 0; j < 20; ++j) {
        int wo = j*4 + ws;
        float y = ftanh(acc[j] + bb);
        ybase[wo] = y;
        s1 += y;
        s2 += y*y;
    }
    s1 += __shfl_down_sync(0xffffffffu, s1, 1, 4);
    s1 += __shfl_down_sync(0xffffffffu, s1, 2, 4);
    s2 += __shfl_down_sync(0xffffffffu, s2, 1, 4);
    s2 += __shfl_down_sync(0xffffffffu, s2, 2, 4);
    if (ws == 0) {
        int pp = b*HOo + ho;
        g_ps1[pp*CO_ + co] = s1;
        g_ps2[pp*CO_ + co] = s2;
    }
}

// ---------------- kernel 3: per-channel mean/var -> scale/shift ----------------
__global__ void reduce_kernel(const float* __restrict__ gamma, const float* __restrict__ beta) {
    __shared__ float sh1[256];
    __shared__ float sh2[256];
    const int co = blockIdx.x;
    const int t  = threadIdx.x;
    float s1 = 0.0f, s2 = 0.0f;
    for (int p = t; p < BB*HOo; p += 256) {
        s1 += g_ps1[p*CO_ + co];
        s2 += g_ps2[p*CO_ + co];
    }
    sh1[t] = s1; sh2[t] = s2;
    __syncthreads();
    for (int s = 128; s > 0; s >>= 1) {
        if (t < s) { sh1[t] += sh1[t+s]; sh2[t] += sh2[t+s]; }
        __syncthreads();
    }
    if (t == 0) {
        const float N = (float)(BB*HOo*WOo);
        float mean = sh1[0] / N;
        float var  = sh2[0] / N - mean*mean;
        float sc = gamma[co] * rsqrtf(var + 1e-5f);
        g_sc[co] = sc;
        g_sh[co] = beta[co] - mean*sc;
    }
}

// ---------------- kernel 4: normalize ----------------
__global__ void norm_kernel(float* __restrict__ out) {
    int t  = blockIdx.x * blockDim.x + threadIdx.x;
    int i0 = t * 4;
    int co = (i0 / (HOo*WOo)) & 63;
    float sc = g_sc[co], sh = g_sh[co];
    float4 v = *(const float4*)(g_y + i0);
    v.x = v.x*sc + sh;
    v.y = v.y*sc + sh;
    v.z = v.z*sc + sh;
    v.w = v.w*sc + sh;
    *(float4*)(out + i0) = v;
}

// ---------------- launcher ----------------
extern "C" void kernel_launch(void* const* d_in, const int* in_sizes, int n_in,
                              void* d_out, int out_size) {
    (void)in_sizes; (void)n_in; (void)out_size;
    const float* x      = (const float*)d_in[0];
    const float* Wx     = (const float*)d_in[1];
    const float* Ul     = (const float*)d_in[2];
    const float* Ut     = (const float*)d_in[3];
    const float* bias   = (const float*)d_in[4];
    const float* conv_w = (const float*)d_in[5];
    const float* conv_b = (const float*)d_in[6];
    const float* gamma  = (const float*)d_in[7];
    const float* beta   = (const float*)d_in[8];
    float* out = (float*)d_out;

    cudaFuncSetAttribute(mdlstm_kernel, cudaFuncAttributeMaxDynamicSharedMemorySize, SM_TOT*4);
    cudaFuncSetAttribute(conv_kernel,   cudaFuncAttributeMaxDynamicSharedMemorySize, (10240+8192)*4);

    prep_kernel<<<7680, 256>>>(x);
    mdlstm_kernel<<<4*NPAIR, 256, SM_TOT*4>>>(Wx, Ul, Ut, bias);
    conv_kernel<<<dim3(HOo, BB), 256, (10240+8192)*4>>>(conv_w, conv_b);
    reduce_kernel<<<CO_, 256>>>(gamma, beta);
    norm_kernel<<<3840, 256>>>(out);
}